// round 9
// baseline (speedup 1.0000x reference)
#include <cuda_runtime.h>

#define NB 8
#define DD 128
#define SS 128
#define MM 16
#define M2 256
#define M3 4096
#define M4 65536

// ---------------- scratch (device globals; no allocation allowed) ----------
__device__ float g_q  [NB * 512 * M3];    // single-axis pools, k = a*128+d
__device__ float g_r  [NB * 768 * M2];    // pair pools,        k = pair*128+d
__device__ float g_t  [NB * 512 * MM];    // triple pools,      k = trip*128+d
__device__ float g_G3 [4 * NB * SS * M3]; // folded cubic fields per placement
__device__ float g_H2 [6 * NB * SS * M2];
__device__ float g_H1 [4 * NB * SS * MM];
__device__ float g_C0 [DD * SS];          // [d][s], b=0
__device__ float g_CB3[4 * 512 * SS];     // [B][k][s], b = 1  + a*4 + B
__device__ float g_CB2[6 * 768 * SS];     // [B][k][s], b = 17 + A*6 + B
__device__ float g_CB1[4 * 512 * SS];     // [B][k][s], b = 53 + A*4 + B

// ---------------- f32x2 helpers --------------------------------------------
__device__ __forceinline__ void fma2(unsigned long long& d,
                                     unsigned long long a,
                                     unsigned long long b) {
    asm("fma.rn.f32x2 %0, %1, %2, %0;" : "+l"(d) : "l"(a), "l"(b));
}
__device__ __forceinline__ unsigned long long pack2(float v) {
    unsigned long long r; unsigned u = __float_as_uint(v);
    asm("mov.b64 %0, {%1, %1};" : "=l"(r) : "r"(u));
    return r;
}
__device__ __forceinline__ float2 unpack2(unsigned long long v) {
    unsigned lo, hi;
    asm("mov.b64 {%0, %1}, %2;" : "=r"(lo), "=r"(hi) : "l"(v));
    float2 f; f.x = __uint_as_float(lo); f.y = __uint_as_float(hi);
    return f;
}

// ---------------- coef repack ----------------------------------------------
__global__ void repack_kernel(const float* __restrict__ coefs) {
    int region = blockIdx.y;
    int idx = blockIdx.x * 256 + threadIdx.x;
    if (region == 0) {
        if (idx < DD * SS) {
            int d = idx >> 7, s = idx & 127;
            g_C0[idx] = coefs[(d * 128 + s) * 69 + 0];
        }
    } else if (region == 1) {
        if (idx < 4 * 512 * SS) {
            int B = idx >> 16; int rem = idx & 65535;
            int k = rem >> 7, s = rem & 127;
            int a = k >> 7, d = k & 127;
            g_CB3[idx] = coefs[(d * 128 + s) * 69 + 1 + a * 4 + B];
        }
    } else if (region == 2) {
        if (idx < 6 * 768 * SS) {
            int B = idx / 98304; int rem = idx - B * 98304;
            int k = rem >> 7, s = rem & 127;
            int A = k >> 7, d = k & 127;
            g_CB2[idx] = coefs[(d * 128 + s) * 69 + 17 + A * 6 + B];
        }
    } else {
        if (idx < 4 * 512 * SS) {
            int B = idx >> 16; int rem = idx & 65535;
            int k = rem >> 7, s = rem & 127;
            int A = k >> 7, d = k & 127;
            g_CB1[idx] = coefs[(d * 128 + s) * 69 + 53 + A * 4 + B];
        }
    }
}

// ---------------- single-axis pools (one streaming pass over x) ------------
// slab padded: [i1][i2][i3] -> i1*272 + i2*17 + i3  (17 coprime 32 => no bank
// conflicts on any of the three reduction access patterns).
__global__ void pool1_kernel(const float* __restrict__ x) {
    int nd = blockIdx.x;                  // n*128 + d
    int n = nd >> 7, d = nd & 127;
    const float* xp = x + (size_t)nd * M4;
    __shared__ float slab[16 * 272];
    __shared__ float q0acc[M3];
    int t = threadIdx.x;                  // 256 threads
    for (int i = t; i < M3; i += 256) q0acc[i] = 0.f;
    float* q0row = g_q + (size_t)(n * 512 + 0 * 128 + d) * M3; // kept (1,2,3)
    float* q1row = g_q + (size_t)(n * 512 + 1 * 128 + d) * M3; // kept (0,2,3)
    float* q2row = g_q + (size_t)(n * 512 + 2 * 128 + d) * M3; // kept (0,1,3)
    float* q3row = g_q + (size_t)(n * 512 + 3 * 128 + d) * M3; // kept (0,1,2)
    int hi = t >> 4, lo = t & 15;
    for (int i0 = 0; i0 < 16; i0++) {
        const float4* xs4 = (const float4*)(xp + (size_t)i0 * M3);
        __syncthreads();
#pragma unroll
        for (int it = 0; it < 4; it++) {
            int i4 = t + it * 256;
            float4 v = xs4[i4];
            int b = i4 * 4, i1 = b >> 8, i2 = (b >> 4) & 15, i3 = b & 15;
            int p = i1 * 272 + i2 * 17 + i3;
            slab[p] = v.x; slab[p + 1] = v.y; slab[p + 2] = v.z; slab[p + 3] = v.w;
            q0acc[b] += v.x; q0acc[b + 1] += v.y;
            q0acc[b + 2] += v.z; q0acc[b + 3] += v.w;
        }
        __syncthreads();
        float s3 = 0.f, s2 = 0.f, s1 = 0.f;
#pragma unroll
        for (int k = 0; k < 16; k++) {
            s3 += slab[hi * 272 + lo * 17 + k];   // t=(i1,i2), sum i3
            s2 += slab[hi * 272 + k * 17 + lo];   // t=(i1,i3), sum i2
            s1 += slab[k * 272 + hi * 17 + lo];   // t=(i2,i3), sum i1
        }
        q3row[i0 * 256 + t] = s3;
        q2row[i0 * 256 + t] = s2;
        q1row[i0 * 256 + t] = s1;
    }
    for (int i = t; i < M3; i += 256) q0row[i] = q0acc[i];
}

// ---------------- pair + triple pools --------------------------------------
__global__ void pool2_kernel() {
    int nd = blockIdx.x;
    int n = nd >> 7, d = nd & 127;
    int t = threadIdx.x;
    __shared__ float rs[6 * 256];
    const int pa[6] = {0, 0, 0, 1, 1, 2};  // pairs lex
    const int pb[6] = {1, 2, 3, 2, 3, 3};
    int w0 = t >> 4, w1 = t & 15;
#pragma unroll
    for (int p = 0; p < 6; p++) {
        const float* src = g_q + (size_t)(n * 512 + pb[p] * 128 + d) * M3;
        int pos = pa[p];       // axis position to pool inside q_{pb}
        float sum = 0.f;
#pragma unroll
        for (int k = 0; k < 16; k++) {
            int idx;
            if (pos == 0)      idx = k * 256 + t;
            else if (pos == 1) idx = w0 * 256 + k * 16 + w1;
            else               idx = t * 16 + k;
            sum += src[idx];
        }
        rs[p * 256 + t] = sum;
        g_r[(size_t)(n * 768 + p * 128 + d) * M2 + t] = sum;
    }
    __syncthreads();
    if (t < 64) {
        // triples lex: (0,1,2)(0,1,3)(0,2,3)(1,2,3)
        const int srcp[4] = {3, 4, 5, 5};  // source pair index
        const int tpos[4] = {0, 0, 0, 1};  // axis position to pool in pair
        int A = t >> 4, w = t & 15;
        const float* rr = rs + srcp[A] * 256;
        float sum = 0.f;
#pragma unroll
        for (int k = 0; k < 16; k++)
            sum += (tpos[A] == 0) ? rr[k * 16 + w] : rr[w * 16 + k];
        g_t[(size_t)(n * 512 + A * 128 + d) * MM + w] = sum;
    }
}

// ---------------- H1: K=512 over triple pools ------------------------------
__global__ void h1_kernel() {
    int B = blockIdx.x >> 3;
    int n = blockIdx.x & 7;
    int t = threadIdx.x;
    __shared__ float ts[512 * MM];
    const float* tsrc = g_t + (size_t)n * 512 * MM;
    for (int i = t; i < 512 * MM; i += 256) ts[i] = tsrc[i];
    __syncthreads();
    int s = t >> 1, wbase = (t & 1) * 8;
    const float* C = g_CB1 + (size_t)B * 512 * SS;
    float acc[8];
#pragma unroll
    for (int j = 0; j < 8; j++) acc[j] = 0.f;
    for (int k = 0; k < 512; k++) {
        float c = C[k * 128 + s];
#pragma unroll
        for (int j = 0; j < 8; j++) acc[j] += c * ts[k * 16 + wbase + j];
    }
#pragma unroll
    for (int j = 0; j < 8; j++)
        g_H1[(size_t)((B * 8 + n) * 128 + s) * MM + wbase + j] = acc[j];
}

// ---------------- shared GEMM core: 128(S) x 128(px) tile, f32x2 FMA -------
template <int KDIM>
__device__ __forceinline__ void gemm_core(const float* __restrict__ A,
                                          const float* __restrict__ X,
                                          int xrowstride, int px_base,
                                          unsigned long long (&acc)[8][4]) {
    __shared__ __align__(16) float As[16][128];
    __shared__ __align__(16) float Xs[16][128];
    int t = threadIdx.x;
    int pg = t & 31, sg = t >> 5;
    for (int k0 = 0; k0 < KDIM; k0 += 16) {
        const float4* a4 = (const float4*)(A + (size_t)k0 * 128);
        float4* as4 = (float4*)&As[0][0];
#pragma unroll
        for (int i = 0; i < 2; i++) as4[t + i * 256] = a4[t + i * 256];
        float4* xs4 = (float4*)&Xs[0][0];
#pragma unroll
        for (int i = 0; i < 2; i++) {
            int li = t + i * 256;
            int r = li >> 5, c = li & 31;
            xs4[li] = ((const float4*)(X + (size_t)(k0 + r) * xrowstride + px_base))[c];
        }
        __syncthreads();
#pragma unroll
        for (int kk = 0; kk < 16; kk++) {
            unsigned long long a[8];
            const ulonglong2* ap = (const ulonglong2*)&As[kk][sg * 16];
#pragma unroll
            for (int i = 0; i < 4; i++) {
                ulonglong2 v = ap[i];
                a[2 * i] = v.x; a[2 * i + 1] = v.y;
            }
#pragma unroll
            for (int j = 0; j < 4; j++) {
                unsigned long long b = pack2(Xs[kk][pg + 32 * j]);
#pragma unroll
                for (int i = 0; i < 8; i++) fma2(acc[i][j], a[i], b);
            }
        }
        __syncthreads();
    }
}

// ---------------- H2 GEMM: K=768 over pair pools ---------------------------
__global__ void __launch_bounds__(256, 2) h2_gemm_kernel() {
    int B = blockIdx.z, n = blockIdx.y;
    int u_base = blockIdx.x * 128;
    unsigned long long acc[8][4];
#pragma unroll
    for (int i = 0; i < 8; i++)
#pragma unroll
        for (int j = 0; j < 4; j++) acc[i][j] = 0ull;
    gemm_core<768>(g_CB2 + (size_t)B * 768 * SS,
                   g_r + (size_t)n * 768 * M2, M2, u_base, acc);
    int t = threadIdx.x, pg = t & 31, sg = t >> 5;
    float* Y = g_H2 + (size_t)(B * 8 + n) * SS * M2;
#pragma unroll
    for (int i = 0; i < 8; i++) {
        int s0 = sg * 16 + 2 * i;
#pragma unroll
        for (int j = 0; j < 4; j++) {
            float2 v = unpack2(acc[i][j]);
            int u = u_base + pg + 32 * j;
            Y[(size_t)s0 * M2 + u] = v.x;
            Y[(size_t)(s0 + 1) * M2 + u] = v.y;
        }
    }
}

// ---------------- H3 GEMM: K=512 stacked pools + fold of H2/H1/bias --------
__global__ void __launch_bounds__(256, 2) h3_gemm_kernel(const float* __restrict__ bias) {
    int B = blockIdx.z, n = blockIdx.y;
    int u_base = blockIdx.x * 128;
    unsigned long long acc[8][4];
#pragma unroll
    for (int i = 0; i < 8; i++)
#pragma unroll
        for (int j = 0; j < 4; j++) acc[i][j] = 0ull;
    gemm_core<512>(g_CB3 + (size_t)B * 512 * SS,
                   g_q + (size_t)n * 512 * M3, M3, u_base, acc);
    int t = threadIdx.x, pg = t & 31, sg = t >> 5;
    int v0 = u_base >> 8;
    int v1b = (u_base >> 4) & 15;
    int v2 = pg & 15, v1l = pg >> 4;
    float* Y = g_G3 + (size_t)(B * 8 + n) * SS * M3;
    const float* H2_0 = g_H2 + (size_t)(0 * 8 + n) * SS * M2; // slots (0,1)
    const float* H2_1 = g_H2 + (size_t)(1 * 8 + n) * SS * M2; // (0,2)
    const float* H2_2 = g_H2 + (size_t)(2 * 8 + n) * SS * M2; // (0,3)
    const float* H2_3 = g_H2 + (size_t)(3 * 8 + n) * SS * M2; // (1,2)
    const float* H2_4 = g_H2 + (size_t)(4 * 8 + n) * SS * M2; // (1,3)
    const float* H2_5 = g_H2 + (size_t)(5 * 8 + n) * SS * M2; // (2,3)
    const float* H1_0 = g_H1 + (size_t)(0 * 8 + n) * SS * MM;
    const float* H1_1 = g_H1 + (size_t)(1 * 8 + n) * SS * MM;
    const float* H1_2 = g_H1 + (size_t)(2 * 8 + n) * SS * MM;
    const float* H1_3 = g_H1 + (size_t)(3 * 8 + n) * SS * MM;
#pragma unroll
    for (int i = 0; i < 8; i++) {
#pragma unroll
        for (int j = 0; j < 4; j++) {
            float2 v = unpack2(acc[i][j]);
            int v1 = v1b + v1l + 2 * j;
            int u = u_base + pg + 32 * j;
#pragma unroll
            for (int h = 0; h < 2; h++) {
                int s = sg * 16 + 2 * i + h;
                float val = h ? v.y : v.x;
                float add = 0.f;
                if (B == 0) {        // slots (0,1,2): fold (0,1)(0,2)(1,2),H1 0/1/2,bias
                    add = H2_0[s * M2 + v0 * 16 + v1]
                        + H2_1[s * M2 + v0 * 16 + v2]
                        + H2_3[s * M2 + v1 * 16 + v2]
                        + H1_0[s * MM + v0] + H1_1[s * MM + v1] + H1_2[s * MM + v2]
                        + bias[s];
                } else if (B == 1) { // slots (0,1,3): fold (0,3)(1,3),H1 3
                    add = H2_2[s * M2 + v0 * 16 + v2]
                        + H2_4[s * M2 + v1 * 16 + v2]
                        + H1_3[s * MM + v2];
                } else if (B == 2) { // slots (0,2,3): fold (2,3)
                    add = H2_5[s * M2 + v1 * 16 + v2];
                }
                Y[(size_t)s * M3 + u] = val + add;
            }
        }
    }
}

// ---------------- main GEMM (b=0) + 4 folded field adds --------------------
__global__ void __launch_bounds__(256, 2) main_gemm_kernel(const float* __restrict__ x,
                                                           float* __restrict__ out) {
    int n = blockIdx.y;
    int px_base = blockIdx.x * 128;
    unsigned long long acc[8][4];
#pragma unroll
    for (int i = 0; i < 8; i++)
#pragma unroll
        for (int j = 0; j < 4; j++) acc[i][j] = 0ull;
    gemm_core<128>(g_C0, x + (size_t)n * DD * M4, M4, px_base, acc);
    int t = threadIdx.x, pg = t & 31, sg = t >> 5;
    int i0 = px_base >> 12;
    int i1 = (px_base >> 8) & 15;
    int i2b = (px_base >> 4) & 15;
    int i3 = pg & 15, i2l = pg >> 4;
    const float* G0 = g_G3 + (size_t)(0 * 8 + n) * SS * M3;  // (i0,i1,i2)
    const float* G1 = g_G3 + (size_t)(1 * 8 + n) * SS * M3;  // (i0,i1,i3)
    const float* G2 = g_G3 + (size_t)(2 * 8 + n) * SS * M3;  // (i0,i2,i3)
    const float* G3p = g_G3 + (size_t)(3 * 8 + n) * SS * M3; // (i1,i2,i3)
    int u1 = i0 * 256 + i1 * 16 + i3;  // constant per thread
#pragma unroll
    for (int i = 0; i < 8; i++) {
        int s0 = sg * 16 + 2 * i;
#pragma unroll
        for (int j = 0; j < 4; j++) {
            float2 v = unpack2(acc[i][j]);
            int i2 = i2b + i2l + 2 * j;
            int u0 = i0 * 256 + i1 * 16 + i2;
            int u2 = i0 * 256 + i2 * 16 + i3;
            int u3 = i1 * 256 + i2 * 16 + i3;
            int px = px_base + pg + 32 * j;
            float r0 = v.x + G0[(size_t)s0 * M3 + u0] + G1[(size_t)s0 * M3 + u1]
                           + G2[(size_t)s0 * M3 + u2] + G3p[(size_t)s0 * M3 + u3];
            float r1 = v.y + G0[(size_t)(s0 + 1) * M3 + u0] + G1[(size_t)(s0 + 1) * M3 + u1]
                           + G2[(size_t)(s0 + 1) * M3 + u2] + G3p[(size_t)(s0 + 1) * M3 + u3];
            out[(size_t)(n * 128 + s0) * M4 + px] = r0;
            out[(size_t)(n * 128 + s0 + 1) * M4 + px] = r1;
        }
    }
}

// ---------------- launch ----------------------------------------------------
extern "C" void kernel_launch(void* const* d_in, const int* in_sizes, int n_in,
                              void* d_out, int out_size) {
    const float* x     = (const float*)d_in[0];
    const float* coefs = (const float*)d_in[1];
    const float* bias  = (const float*)d_in[2];
    float* out = (float*)d_out;

    repack_kernel<<<dim3(2304, 4), 256>>>(coefs);
    pool1_kernel<<<NB * DD, 256>>>(x);
    pool2_kernel<<<NB * DD, 256>>>();
    h1_kernel<<<4 * NB, 256>>>();
    h2_gemm_kernel<<<dim3(M2 / 128, NB, 6), 256>>>();
    h3_gemm_kernel<<<dim3(M3 / 128, NB, 4), 256>>>(bias);
    main_gemm_kernel<<<dim3(M4 / 128, NB), 256>>>(x, out);
}

// round 10
// speedup vs baseline: 1.0003x; 1.0003x over previous
#include <cuda_runtime.h>

#define NB 8
#define DD 128
#define SS 128
#define MM 16
#define M2 256
#define M3 4096
#define M4 65536

// ---------------- scratch (device globals; no allocation allowed) ----------
__device__ float g_q  [NB * 512 * M3];    // single-axis pools, k = a*128+d
__device__ float g_r  [NB * 768 * M2];    // pair pools,        k = pair*128+d
__device__ float g_t  [NB * 512 * MM];    // triple pools,      k = trip*128+d
__device__ float g_G3 [4 * NB * SS * M3]; // folded cubic fields per placement
__device__ float g_H2 [6 * NB * SS * M2];
__device__ float g_H1 [4 * NB * SS * MM];
__device__ float g_C0 [DD * SS];          // [d][s], b=0
__device__ float g_CB3[4 * 512 * SS];     // [B][k][s], b = 1  + a*4 + B
__device__ float g_CB2[6 * 768 * SS];     // [B][k][s], b = 17 + A*6 + B
__device__ float g_CB1[4 * 512 * SS];     // [B][k][s], b = 53 + A*4 + B

// ---------------- f32x2 helpers --------------------------------------------
__device__ __forceinline__ void fma2(unsigned long long& d,
                                     unsigned long long a,
                                     unsigned long long b) {
    asm("fma.rn.f32x2 %0, %1, %2, %0;" : "+l"(d) : "l"(a), "l"(b));
}
__device__ __forceinline__ unsigned long long pack2(float v) {
    unsigned long long r; unsigned u = __float_as_uint(v);
    asm("mov.b64 %0, {%1, %1};" : "=l"(r) : "r"(u));
    return r;
}
__device__ __forceinline__ float2 unpack2(unsigned long long v) {
    unsigned lo, hi;
    asm("mov.b64 {%0, %1}, %2;" : "=r"(lo), "=r"(hi) : "l"(v));
    float2 f; f.x = __uint_as_float(lo); f.y = __uint_as_float(hi);
    return f;
}

// ---------------- coef repack ----------------------------------------------
__global__ void repack_kernel(const float* __restrict__ coefs) {
    int region = blockIdx.y;
    int idx = blockIdx.x * 256 + threadIdx.x;
    if (region == 0) {
        if (idx < DD * SS) {
            int d = idx >> 7, s = idx & 127;
            g_C0[idx] = coefs[(d * 128 + s) * 69 + 0];
        }
    } else if (region == 1) {
        if (idx < 4 * 512 * SS) {
            int B = idx >> 16; int rem = idx & 65535;
            int k = rem >> 7, s = rem & 127;
            int a = k >> 7, d = k & 127;
            g_CB3[idx] = coefs[(d * 128 + s) * 69 + 1 + a * 4 + B];
        }
    } else if (region == 2) {
        if (idx < 6 * 768 * SS) {
            int B = idx / 98304; int rem = idx - B * 98304;
            int k = rem >> 7, s = rem & 127;
            int A = k >> 7, d = k & 127;
            g_CB2[idx] = coefs[(d * 128 + s) * 69 + 17 + A * 6 + B];
        }
    } else {
        if (idx < 4 * 512 * SS) {
            int B = idx >> 16; int rem = idx & 65535;
            int k = rem >> 7, s = rem & 127;
            int A = k >> 7, d = k & 127;
            g_CB1[idx] = coefs[(d * 128 + s) * 69 + 53 + A * 4 + B];
        }
    }
}

// ---------------- single-axis pools (one streaming pass over x) ------------
// slab padded: [i1][i2][i3] -> i1*272 + i2*17 + i3  (17 coprime 32 => no bank
// conflicts on any of the three reduction access patterns).
__global__ void pool1_kernel(const float* __restrict__ x) {
    int nd = blockIdx.x;                  // n*128 + d
    int n = nd >> 7, d = nd & 127;
    const float* xp = x + (size_t)nd * M4;
    __shared__ float slab[16 * 272];
    __shared__ float q0acc[M3];
    int t = threadIdx.x;                  // 256 threads
    for (int i = t; i < M3; i += 256) q0acc[i] = 0.f;
    float* q0row = g_q + (size_t)(n * 512 + 0 * 128 + d) * M3; // kept (1,2,3)
    float* q1row = g_q + (size_t)(n * 512 + 1 * 128 + d) * M3; // kept (0,2,3)
    float* q2row = g_q + (size_t)(n * 512 + 2 * 128 + d) * M3; // kept (0,1,3)
    float* q3row = g_q + (size_t)(n * 512 + 3 * 128 + d) * M3; // kept (0,1,2)
    int hi = t >> 4, lo = t & 15;
    for (int i0 = 0; i0 < 16; i0++) {
        const float4* xs4 = (const float4*)(xp + (size_t)i0 * M3);
        __syncthreads();
#pragma unroll
        for (int it = 0; it < 4; it++) {
            int i4 = t + it * 256;
            float4 v = xs4[i4];
            int b = i4 * 4, i1 = b >> 8, i2 = (b >> 4) & 15, i3 = b & 15;
            int p = i1 * 272 + i2 * 17 + i3;
            slab[p] = v.x; slab[p + 1] = v.y; slab[p + 2] = v.z; slab[p + 3] = v.w;
            q0acc[b] += v.x; q0acc[b + 1] += v.y;
            q0acc[b + 2] += v.z; q0acc[b + 3] += v.w;
        }
        __syncthreads();
        float s3 = 0.f, s2 = 0.f, s1 = 0.f;
#pragma unroll
        for (int k = 0; k < 16; k++) {
            s3 += slab[hi * 272 + lo * 17 + k];   // t=(i1,i2), sum i3
            s2 += slab[hi * 272 + k * 17 + lo];   // t=(i1,i3), sum i2
            s1 += slab[k * 272 + hi * 17 + lo];   // t=(i2,i3), sum i1
        }
        q3row[i0 * 256 + t] = s3;
        q2row[i0 * 256 + t] = s2;
        q1row[i0 * 256 + t] = s1;
    }
    for (int i = t; i < M3; i += 256) q0row[i] = q0acc[i];
}

// ---------------- pair + triple pools --------------------------------------
__global__ void pool2_kernel() {
    int nd = blockIdx.x;
    int n = nd >> 7, d = nd & 127;
    int t = threadIdx.x;
    __shared__ float rs[6 * 256];
    const int pa[6] = {0, 0, 0, 1, 1, 2};  // pairs lex
    const int pb[6] = {1, 2, 3, 2, 3, 3};
    int w0 = t >> 4, w1 = t & 15;
#pragma unroll
    for (int p = 0; p < 6; p++) {
        const float* src = g_q + (size_t)(n * 512 + pb[p] * 128 + d) * M3;
        int pos = pa[p];       // axis position to pool inside q_{pb}
        float sum = 0.f;
#pragma unroll
        for (int k = 0; k < 16; k++) {
            int idx;
            if (pos == 0)      idx = k * 256 + t;
            else if (pos == 1) idx = w0 * 256 + k * 16 + w1;
            else               idx = t * 16 + k;
            sum += src[idx];
        }
        rs[p * 256 + t] = sum;
        g_r[(size_t)(n * 768 + p * 128 + d) * M2 + t] = sum;
    }
    __syncthreads();
    if (t < 64) {
        // triples lex: (0,1,2)(0,1,3)(0,2,3)(1,2,3)
        const int srcp[4] = {3, 4, 5, 5};  // source pair index
        const int tpos[4] = {0, 0, 0, 1};  // axis position to pool in pair
        int A = t >> 4, w = t & 15;
        const float* rr = rs + srcp[A] * 256;
        float sum = 0.f;
#pragma unroll
        for (int k = 0; k < 16; k++)
            sum += (tpos[A] == 0) ? rr[k * 16 + w] : rr[w * 16 + k];
        g_t[(size_t)(n * 512 + A * 128 + d) * MM + w] = sum;
    }
}

// ---------------- H1: K=512 over triple pools ------------------------------
__global__ void h1_kernel() {
    int B = blockIdx.x >> 3;
    int n = blockIdx.x & 7;
    int t = threadIdx.x;
    __shared__ float ts[512 * MM];
    const float* tsrc = g_t + (size_t)n * 512 * MM;
    for (int i = t; i < 512 * MM; i += 256) ts[i] = tsrc[i];
    __syncthreads();
    int s = t >> 1, wbase = (t & 1) * 8;
    const float* C = g_CB1 + (size_t)B * 512 * SS;
    float acc[8];
#pragma unroll
    for (int j = 0; j < 8; j++) acc[j] = 0.f;
    for (int k = 0; k < 512; k++) {
        float c = C[k * 128 + s];
#pragma unroll
        for (int j = 0; j < 8; j++) acc[j] += c * ts[k * 16 + wbase + j];
    }
#pragma unroll
    for (int j = 0; j < 8; j++)
        g_H1[(size_t)((B * 8 + n) * 128 + s) * MM + wbase + j] = acc[j];
}

// ---------------- shared GEMM core: 128(S) x 128(px) tile, f32x2 FMA -------
template <int KDIM>
__device__ __forceinline__ void gemm_core(const float* __restrict__ A,
                                          const float* __restrict__ X,
                                          int xrowstride, int px_base,
                                          unsigned long long (&acc)[8][4]) {
    __shared__ __align__(16) float As[16][128];
    __shared__ __align__(16) float Xs[16][128];
    int t = threadIdx.x;
    int pg = t & 31, sg = t >> 5;
    for (int k0 = 0; k0 < KDIM; k0 += 16) {
        const float4* a4 = (const float4*)(A + (size_t)k0 * 128);
        float4* as4 = (float4*)&As[0][0];
#pragma unroll
        for (int i = 0; i < 2; i++) as4[t + i * 256] = a4[t + i * 256];
        float4* xs4 = (float4*)&Xs[0][0];
#pragma unroll
        for (int i = 0; i < 2; i++) {
            int li = t + i * 256;
            int r = li >> 5, c = li & 31;
            xs4[li] = ((const float4*)(X + (size_t)(k0 + r) * xrowstride + px_base))[c];
        }
        __syncthreads();
#pragma unroll
        for (int kk = 0; kk < 16; kk++) {
            unsigned long long a[8];
            const ulonglong2* ap = (const ulonglong2*)&As[kk][sg * 16];
#pragma unroll
            for (int i = 0; i < 4; i++) {
                ulonglong2 v = ap[i];
                a[2 * i] = v.x; a[2 * i + 1] = v.y;
            }
#pragma unroll
            for (int j = 0; j < 4; j++) {
                unsigned long long b = pack2(Xs[kk][pg + 32 * j]);
#pragma unroll
                for (int i = 0; i < 8; i++) fma2(acc[i][j], a[i], b);
            }
        }
        __syncthreads();
    }
}

// ---------------- H2 GEMM: K=768 over pair pools ---------------------------
__global__ void __launch_bounds__(256, 2) h2_gemm_kernel() {
    int B = blockIdx.z, n = blockIdx.y;
    int u_base = blockIdx.x * 128;
    unsigned long long acc[8][4];
#pragma unroll
    for (int i = 0; i < 8; i++)
#pragma unroll
        for (int j = 0; j < 4; j++) acc[i][j] = 0ull;
    gemm_core<768>(g_CB2 + (size_t)B * 768 * SS,
                   g_r + (size_t)n * 768 * M2, M2, u_base, acc);
    int t = threadIdx.x, pg = t & 31, sg = t >> 5;
    float* Y = g_H2 + (size_t)(B * 8 + n) * SS * M2;
#pragma unroll
    for (int i = 0; i < 8; i++) {
        int s0 = sg * 16 + 2 * i;
#pragma unroll
        for (int j = 0; j < 4; j++) {
            float2 v = unpack2(acc[i][j]);
            int u = u_base + pg + 32 * j;
            Y[(size_t)s0 * M2 + u] = v.x;
            Y[(size_t)(s0 + 1) * M2 + u] = v.y;
        }
    }
}

// ---------------- H3 GEMM: K=512 stacked pools + fold of H2/H1/bias --------
__global__ void __launch_bounds__(256, 2) h3_gemm_kernel(const float* __restrict__ bias) {
    int B = blockIdx.z, n = blockIdx.y;
    int u_base = blockIdx.x * 128;
    unsigned long long acc[8][4];
#pragma unroll
    for (int i = 0; i < 8; i++)
#pragma unroll
        for (int j = 0; j < 4; j++) acc[i][j] = 0ull;
    gemm_core<512>(g_CB3 + (size_t)B * 512 * SS,
                   g_q + (size_t)n * 512 * M3, M3, u_base, acc);
    int t = threadIdx.x, pg = t & 31, sg = t >> 5;
    int v0 = u_base >> 8;
    int v1b = (u_base >> 4) & 15;
    int v2 = pg & 15, v1l = pg >> 4;
    float* Y = g_G3 + (size_t)(B * 8 + n) * SS * M3;
    const float* H2_0 = g_H2 + (size_t)(0 * 8 + n) * SS * M2; // slots (0,1)
    const float* H2_1 = g_H2 + (size_t)(1 * 8 + n) * SS * M2; // (0,2)
    const float* H2_2 = g_H2 + (size_t)(2 * 8 + n) * SS * M2; // (0,3)
    const float* H2_3 = g_H2 + (size_t)(3 * 8 + n) * SS * M2; // (1,2)
    const float* H2_4 = g_H2 + (size_t)(4 * 8 + n) * SS * M2; // (1,3)
    const float* H2_5 = g_H2 + (size_t)(5 * 8 + n) * SS * M2; // (2,3)
    const float* H1_0 = g_H1 + (size_t)(0 * 8 + n) * SS * MM;
    const float* H1_1 = g_H1 + (size_t)(1 * 8 + n) * SS * MM;
    const float* H1_2 = g_H1 + (size_t)(2 * 8 + n) * SS * MM;
    const float* H1_3 = g_H1 + (size_t)(3 * 8 + n) * SS * MM;
#pragma unroll
    for (int i = 0; i < 8; i++) {
#pragma unroll
        for (int j = 0; j < 4; j++) {
            float2 v = unpack2(acc[i][j]);
            int v1 = v1b + v1l + 2 * j;
            int u = u_base + pg + 32 * j;
#pragma unroll
            for (int h = 0; h < 2; h++) {
                int s = sg * 16 + 2 * i + h;
                float val = h ? v.y : v.x;
                float add = 0.f;
                if (B == 0) {        // slots (0,1,2): fold (0,1)(0,2)(1,2),H1 0/1/2,bias
                    add = H2_0[s * M2 + v0 * 16 + v1]
                        + H2_1[s * M2 + v0 * 16 + v2]
                        + H2_3[s * M2 + v1 * 16 + v2]
                        + H1_0[s * MM + v0] + H1_1[s * MM + v1] + H1_2[s * MM + v2]
                        + bias[s];
                } else if (B == 1) { // slots (0,1,3): fold (0,3)(1,3),H1 3
                    add = H2_2[s * M2 + v0 * 16 + v2]
                        + H2_4[s * M2 + v1 * 16 + v2]
                        + H1_3[s * MM + v2];
                } else if (B == 2) { // slots (0,2,3): fold (2,3)
                    add = H2_5[s * M2 + v1 * 16 + v2];
                }
                Y[(size_t)s * M3 + u] = val + add;
            }
        }
    }
}

// ---------------- main GEMM (b=0) + 4 folded field adds --------------------
__global__ void __launch_bounds__(256, 2) main_gemm_kernel(const float* __restrict__ x,
                                                           float* __restrict__ out) {
    int n = blockIdx.y;
    int px_base = blockIdx.x * 128;
    unsigned long long acc[8][4];
#pragma unroll
    for (int i = 0; i < 8; i++)
#pragma unroll
        for (int j = 0; j < 4; j++) acc[i][j] = 0ull;
    gemm_core<128>(g_C0, x + (size_t)n * DD * M4, M4, px_base, acc);
    int t = threadIdx.x, pg = t & 31, sg = t >> 5;
    int i0 = px_base >> 12;
    int i1 = (px_base >> 8) & 15;
    int i2b = (px_base >> 4) & 15;
    int i3 = pg & 15, i2l = pg >> 4;
    const float* G0 = g_G3 + (size_t)(0 * 8 + n) * SS * M3;  // (i0,i1,i2)
    const float* G1 = g_G3 + (size_t)(1 * 8 + n) * SS * M3;  // (i0,i1,i3)
    const float* G2 = g_G3 + (size_t)(2 * 8 + n) * SS * M3;  // (i0,i2,i3)
    const float* G3p = g_G3 + (size_t)(3 * 8 + n) * SS * M3; // (i1,i2,i3)
    int u1 = i0 * 256 + i1 * 16 + i3;  // constant per thread
#pragma unroll
    for (int i = 0; i < 8; i++) {
        int s0 = sg * 16 + 2 * i;
#pragma unroll
        for (int j = 0; j < 4; j++) {
            float2 v = unpack2(acc[i][j]);
            int i2 = i2b + i2l + 2 * j;
            int u0 = i0 * 256 + i1 * 16 + i2;
            int u2 = i0 * 256 + i2 * 16 + i3;
            int u3 = i1 * 256 + i2 * 16 + i3;
            int px = px_base + pg + 32 * j;
            float r0 = v.x + G0[(size_t)s0 * M3 + u0] + G1[(size_t)s0 * M3 + u1]
                           + G2[(size_t)s0 * M3 + u2] + G3p[(size_t)s0 * M3 + u3];
            float r1 = v.y + G0[(size_t)(s0 + 1) * M3 + u0] + G1[(size_t)(s0 + 1) * M3 + u1]
                           + G2[(size_t)(s0 + 1) * M3 + u2] + G3p[(size_t)(s0 + 1) * M3 + u3];
            out[(size_t)(n * 128 + s0) * M4 + px] = r0;
            out[(size_t)(n * 128 + s0 + 1) * M4 + px] = r1;
        }
    }
}

// ---------------- launch ----------------------------------------------------
extern "C" void kernel_launch(void* const* d_in, const int* in_sizes, int n_in,
                              void* d_out, int out_size) {
    const float* x     = (const float*)d_in[0];
    const float* coefs = (const float*)d_in[1];
    const float* bias  = (const float*)d_in[2];
    float* out = (float*)d_out;

    repack_kernel<<<dim3(2304, 4), 256>>>(coefs);
    pool1_kernel<<<NB * DD, 256>>>(x);
    pool2_kernel<<<NB * DD, 256>>>();
    h1_kernel<<<4 * NB, 256>>>();
    h2_gemm_kernel<<<dim3(M2 / 128, NB, 6), 256>>>();
    h3_gemm_kernel<<<dim3(M3 / 128, NB, 4), 256>>>(bias);
    main_gemm_kernel<<<dim3(M4 / 128, NB), 256>>>(x, out);
}